// round 3
// baseline (speedup 1.0000x reference)
#include <cuda_runtime.h>
#include <math.h>

// Problem geometry
#define H_IN   384
#define W_IN   512
#define H_OUT  374   // 384 - 10
#define W_OUT  502   // 512 - 10
#define NCH    48    // 16 * 3
#define TOTAL_OUT 9011904.0  // 48 * 374 * 502

// Tiling
#define TX 64        // output cols per tile
#define TY 32        // output rows per tile
#define IN_TX 74     // TX + 10
#define IN_TY 42     // TY + 10
#define SX_STRIDE 76 // padded row stride for input tiles (16B-aligned rows)
#define TILES_X 8    // ceil(502/64)
#define TILES_Y 12   // ceil(374/32)

__device__ double g_sum;

__global__ void zero_kernel() { g_sum = 0.0; }

__global__ __launch_bounds__(256, 2)
void ssim_kernel(const float* __restrict__ X, const float* __restrict__ Y) {
    extern __shared__ float smem[];
    float* sX = smem;                          // 42*76
    float* sY = sX + IN_TY * SX_STRIDE;        // 42*76
    float* hB = sY + IN_TY * SX_STRIDE;        // 5 arrays of 42*64 (h-blurred fields)

    const int tid = threadIdx.x;
    const int tx0 = blockIdx.x * TX;
    const int ty0 = blockIdx.y * TY;
    const size_t chOff = (size_t)blockIdx.z * (H_IN * W_IN);
    const float* Xc = X + chOff;
    const float* Yc = Y + chOff;

    // ---- load input halo tiles (zero-fill OOB; OOB only feeds masked outputs)
    for (int i = tid; i < IN_TY * IN_TX; i += 256) {
        int r = i / IN_TX;
        int c = i - r * IN_TX;
        int gr = ty0 + r, gc = tx0 + c;
        float xv = 0.f, yv = 0.f;
        if (gr < H_IN && gc < W_IN) {
            xv = Xc[gr * W_IN + gc];
            yv = Yc[gr * W_IN + gc];
        }
        sX[r * SX_STRIDE + c] = xv;
        sY[r * SX_STRIDE + c] = yv;
    }

    // ---- gaussian weights (match reference fp32 exp/normalize)
    float w[11];
    {
        float s = 0.f;
#pragma unroll
        for (int k = 0; k < 11; ++k) {
            float d = (float)(k - 5);
            w[k] = expf(-(d * d) / 4.5f);
            s += w[k];
        }
        float inv = 1.f / s;
#pragma unroll
        for (int k = 0; k < 11; ++k) w[k] *= inv;
    }
    __syncthreads();

    // ---- horizontal blur: 42 rows x 16 groups of 4 cols, products on the fly
    for (int i = tid; i < IN_TY * 16; i += 256) {
        int r = i >> 4;
        int c0 = (i & 15) * 4;
        const float* rx = sX + r * SX_STRIDE + c0;
        const float* ry = sY + r * SX_STRIDE + c0;
        float vx[16], vy[16];
#pragma unroll
        for (int q = 0; q < 4; ++q) {
            float4 a = reinterpret_cast<const float4*>(rx)[q];
            float4 b = reinterpret_cast<const float4*>(ry)[q];
            vx[4*q+0] = a.x; vx[4*q+1] = a.y; vx[4*q+2] = a.z; vx[4*q+3] = a.w;
            vy[4*q+0] = b.x; vy[4*q+1] = b.y; vy[4*q+2] = b.z; vy[4*q+3] = b.w;
        }
        float m1[4] = {0,0,0,0}, m2[4] = {0,0,0,0};
        float xx[4] = {0,0,0,0}, yy[4] = {0,0,0,0}, xy[4] = {0,0,0,0};
#pragma unroll
        for (int k = 0; k < 11; ++k) {
            float wk = w[k];
#pragma unroll
            for (int o = 0; o < 4; ++o) {
                float xv = vx[k + o], yv = vy[k + o];
                float t = wk * xv, u = wk * yv;
                m1[o] += t;
                m2[o] += u;
                xx[o] = fmaf(t, xv, xx[o]);
                yy[o] = fmaf(u, yv, yy[o]);
                xy[o] = fmaf(t, yv, xy[o]);
            }
        }
        int base = r * TX + c0;
        reinterpret_cast<float4*>(hB + 0 * IN_TY * TX + base)[0] = make_float4(m1[0], m1[1], m1[2], m1[3]);
        reinterpret_cast<float4*>(hB + 1 * IN_TY * TX + base)[0] = make_float4(m2[0], m2[1], m2[2], m2[3]);
        reinterpret_cast<float4*>(hB + 2 * IN_TY * TX + base)[0] = make_float4(xx[0], xx[1], xx[2], xx[3]);
        reinterpret_cast<float4*>(hB + 3 * IN_TY * TX + base)[0] = make_float4(yy[0], yy[1], yy[2], yy[3]);
        reinterpret_cast<float4*>(hB + 4 * IN_TY * TX + base)[0] = make_float4(xy[0], xy[1], xy[2], xy[3]);
    }
    __syncthreads();

    // ---- vertical blur + ssim map: each thread does 8 output rows of one column
    float local = 0.f;
    {
        int c  = tid & 63;
        int r0 = (tid >> 6) * 8;
        const float* h0 = hB + 0 * IN_TY * TX + c;
        const float* h1 = hB + 1 * IN_TY * TX + c;
        const float* h2 = hB + 2 * IN_TY * TX + c;
        const float* h3 = hB + 3 * IN_TY * TX + c;
        const float* h4 = hB + 4 * IN_TY * TX + c;

        float a0[8], a1[8], a2[8], a3[8], a4[8];
#pragma unroll
        for (int o = 0; o < 8; ++o) { a0[o] = a1[o] = a2[o] = a3[o] = a4[o] = 0.f; }

#pragma unroll
        for (int k = 0; k < 18; ++k) {
            int off = (r0 + k) * TX;
            float v0 = h0[off];
            float v1 = h1[off];
            float v2 = h2[off];
            float v3 = h3[off];
            float v4 = h4[off];
#pragma unroll
            for (int o = 0; o < 8; ++o) {
                int t = k - o;
                if (t >= 0 && t < 11) {
                    float wk = w[t];
                    a0[o] = fmaf(wk, v0, a0[o]);
                    a1[o] = fmaf(wk, v1, a1[o]);
                    a2[o] = fmaf(wk, v2, a2[o]);
                    a3[o] = fmaf(wk, v3, a3[o]);
                    a4[o] = fmaf(wk, v4, a4[o]);
                }
            }
        }

        int gc = tx0 + c;
        const float C1 = 1e-4f, C2 = 9e-4f;
#pragma unroll
        for (int o = 0; o < 8; ++o) {
            int gr = ty0 + r0 + o;
            if (gr < H_OUT && gc < W_OUT) {
                float mu1 = a0[o], mu2 = a1[o];
                float mu1s = mu1 * mu1;
                float mu2s = mu2 * mu2;
                float m12  = mu1 * mu2;
                float s1  = a2[o] - mu1s;
                float s2  = a3[o] - mu2s;
                float s12 = a4[o] - m12;
                float num = (2.f * m12 + C1) * (2.f * s12 + C2);
                float den = (mu1s + mu2s + C1) * (s1 + s2 + C2);
                local += __fdividef(num, den);
            }
        }
    }

    // ---- block reduction + single double atomic
#pragma unroll
    for (int off = 16; off; off >>= 1)
        local += __shfl_xor_sync(0xffffffffu, local, off);

    __shared__ float red[8];
    int lane = tid & 31, wid = tid >> 5;
    if (lane == 0) red[wid] = local;
    __syncthreads();
    if (tid == 0) {
        float s = 0.f;
#pragma unroll
        for (int i2 = 0; i2 < 8; ++i2) s += red[i2];
        atomicAdd(&g_sum, (double)s);
    }
}

__global__ void finalize_kernel(float* out, int n) {
    float v = (float)(1.0 - g_sum / TOTAL_OUT);
    for (int i = threadIdx.x; i < n; i += blockDim.x) out[i] = v;
}

extern "C" void kernel_launch(void* const* d_in, const int* in_sizes, int n_in,
                              void* d_out, int out_size) {
    const float* pred   = (const float*)d_in[0];
    const float* target = (const float*)d_in[1];

    constexpr size_t SMEM = (size_t)(2 * IN_TY * SX_STRIDE + 5 * IN_TY * TX) * sizeof(float);
    cudaFuncSetAttribute(ssim_kernel, cudaFuncAttributeMaxDynamicSharedMemorySize, (int)SMEM);

    zero_kernel<<<1, 1>>>();
    dim3 grid(TILES_X, TILES_Y, NCH);
    ssim_kernel<<<grid, 256, SMEM>>>(pred, target);
    finalize_kernel<<<1, 32>>>((float*)d_out, out_size);
}

// round 4
// speedup vs baseline: 1.1248x; 1.1248x over previous
#include <cuda_runtime.h>
#include <math.h>

// Problem geometry
#define H_IN   384
#define W_IN   512
#define H_OUT  374   // 384 - 10
#define W_OUT  502   // 512 - 10
#define NCH    48    // 16 * 3
#define TOTAL_OUT 9011904.0  // 48 * 374 * 502

// Tiling
#define TX 64        // output cols per tile
#define TY 32        // output rows per tile
#define IN_TX 74     // TX + 10
#define IN_TY 42     // TY + 10
#define SX_STRIDE 76 // padded row stride for input tiles (16B-aligned rows)
#define TILES_X 8    // ceil(502/64)
#define TILES_Y 12   // ceil(374/32)
#define NBLOCKS (TILES_X * TILES_Y * NCH)   // 4608

// Gaussian weights (win=11, sigma=1.5), baked as literals so ptxas emits
// imm-form FFMA (rt_SMSP=1, 2x throughput vs 3-reg FFMA).
#define GW0 0.00102838f
#define GW1 0.00759874f
#define GW2 0.03600077f
#define GW3 0.10936073f
#define GW4 0.21300553f
#define GW5 0.26601171f

__device__ double g_part[NBLOCKS];

__global__ __launch_bounds__(256, 2)
void ssim_kernel(const float* __restrict__ X, const float* __restrict__ Y) {
    constexpr float W[11] = {GW0, GW1, GW2, GW3, GW4, GW5, GW4, GW3, GW2, GW1, GW0};

    extern __shared__ float smem[];
    float* sX = smem;                          // 42*76
    float* sY = sX + IN_TY * SX_STRIDE;        // 42*76
    float* hB = sY + IN_TY * SX_STRIDE;        // 5 arrays of 42*64 (h-blurred fields)

    const int tid = threadIdx.x;
    const int tx0 = blockIdx.x * TX;
    const int ty0 = blockIdx.y * TY;
    const size_t chOff = (size_t)blockIdx.z * (H_IN * W_IN);
    const float* Xc = X + chOff;
    const float* Yc = Y + chOff;

    // ---- load input halo tiles (zero-fill OOB; OOB only feeds masked outputs)
    for (int i = tid; i < IN_TY * IN_TX; i += 256) {
        int r = i / IN_TX;
        int c = i - r * IN_TX;
        int gr = ty0 + r, gc = tx0 + c;
        float xv = 0.f, yv = 0.f;
        if (gr < H_IN && gc < W_IN) {
            xv = Xc[gr * W_IN + gc];
            yv = Yc[gr * W_IN + gc];
        }
        sX[r * SX_STRIDE + c] = xv;
        sY[r * SX_STRIDE + c] = yv;
    }
    __syncthreads();

    // ---- horizontal blur: 42 rows x 16 groups of 4 cols
    // Products formed once into register arrays; all taps are imm-form FFMA.
    for (int i = tid; i < IN_TY * 16; i += 256) {
        int r = i >> 4;
        int c0 = (i & 15) * 4;
        const float* rx = sX + r * SX_STRIDE + c0;
        const float* ry = sY + r * SX_STRIDE + c0;
        float vx[16], vy[16];
#pragma unroll
        for (int q = 0; q < 4; ++q) {
            float4 a = reinterpret_cast<const float4*>(rx)[q];
            float4 b = reinterpret_cast<const float4*>(ry)[q];
            vx[4*q+0] = a.x; vx[4*q+1] = a.y; vx[4*q+2] = a.z; vx[4*q+3] = a.w;
            vy[4*q+0] = b.x; vy[4*q+1] = b.y; vy[4*q+2] = b.z; vy[4*q+3] = b.w;
        }
        float pxx[14], pyy[14], pxy[14];
#pragma unroll
        for (int j = 0; j < 14; ++j) {
            pxx[j] = vx[j] * vx[j];
            pyy[j] = vy[j] * vy[j];
            pxy[j] = vx[j] * vy[j];
        }
        float m1[4] = {0,0,0,0}, m2[4] = {0,0,0,0};
        float xx[4] = {0,0,0,0}, yy[4] = {0,0,0,0}, xy[4] = {0,0,0,0};
#pragma unroll
        for (int k = 0; k < 11; ++k) {
#pragma unroll
            for (int o = 0; o < 4; ++o) {
                m1[o] = fmaf(W[k], vx[k + o],  m1[o]);
                m2[o] = fmaf(W[k], vy[k + o],  m2[o]);
                xx[o] = fmaf(W[k], pxx[k + o], xx[o]);
                yy[o] = fmaf(W[k], pyy[k + o], yy[o]);
                xy[o] = fmaf(W[k], pxy[k + o], xy[o]);
            }
        }
        int base = r * TX + c0;
        reinterpret_cast<float4*>(hB + 0 * IN_TY * TX + base)[0] = make_float4(m1[0], m1[1], m1[2], m1[3]);
        reinterpret_cast<float4*>(hB + 1 * IN_TY * TX + base)[0] = make_float4(m2[0], m2[1], m2[2], m2[3]);
        reinterpret_cast<float4*>(hB + 2 * IN_TY * TX + base)[0] = make_float4(xx[0], xx[1], xx[2], xx[3]);
        reinterpret_cast<float4*>(hB + 3 * IN_TY * TX + base)[0] = make_float4(yy[0], yy[1], yy[2], yy[3]);
        reinterpret_cast<float4*>(hB + 4 * IN_TY * TX + base)[0] = make_float4(xy[0], xy[1], xy[2], xy[3]);
    }
    __syncthreads();

    // ---- vertical blur + ssim map: each thread does 8 output rows of one column
    float local = 0.f;
    {
        int c  = tid & 63;
        int r0 = (tid >> 6) * 8;
        const float* h0 = hB + 0 * IN_TY * TX + c;
        const float* h1 = hB + 1 * IN_TY * TX + c;
        const float* h2 = hB + 2 * IN_TY * TX + c;
        const float* h3 = hB + 3 * IN_TY * TX + c;
        const float* h4 = hB + 4 * IN_TY * TX + c;

        float a0[8], a1[8], a2[8], a3[8], a4[8];
#pragma unroll
        for (int o = 0; o < 8; ++o) { a0[o] = a1[o] = a2[o] = a3[o] = a4[o] = 0.f; }

#pragma unroll
        for (int k = 0; k < 18; ++k) {
            int off = (r0 + k) * TX;
            float v0 = h0[off];
            float v1 = h1[off];
            float v2 = h2[off];
            float v3 = h3[off];
            float v4 = h4[off];
#pragma unroll
            for (int o = 0; o < 8; ++o) {
                int t = k - o;
                if (t >= 0 && t < 11) {
                    a0[o] = fmaf(W[t], v0, a0[o]);
                    a1[o] = fmaf(W[t], v1, a1[o]);
                    a2[o] = fmaf(W[t], v2, a2[o]);
                    a3[o] = fmaf(W[t], v3, a3[o]);
                    a4[o] = fmaf(W[t], v4, a4[o]);
                }
            }
        }

        int gc = tx0 + c;
        const float C1 = 1e-4f, C2 = 9e-4f;
#pragma unroll
        for (int o = 0; o < 8; ++o) {
            int gr = ty0 + r0 + o;
            if (gr < H_OUT && gc < W_OUT) {
                float mu1 = a0[o], mu2 = a1[o];
                float mu1s = mu1 * mu1;
                float mu2s = mu2 * mu2;
                float m12  = mu1 * mu2;
                float s1  = a2[o] - mu1s;
                float s2  = a3[o] - mu2s;
                float s12 = a4[o] - m12;
                float num = (2.f * m12 + C1) * (2.f * s12 + C2);
                float den = (mu1s + mu2s + C1) * (s1 + s2 + C2);
                local += __fdividef(num, den);
            }
        }
    }

    // ---- block reduction, one partial slot per block (no atomics, no zeroing)
#pragma unroll
    for (int off = 16; off; off >>= 1)
        local += __shfl_xor_sync(0xffffffffu, local, off);

    __shared__ float red[8];
    int lane = tid & 31, wid = tid >> 5;
    if (lane == 0) red[wid] = local;
    __syncthreads();
    if (tid == 0) {
        float s = 0.f;
#pragma unroll
        for (int i2 = 0; i2 < 8; ++i2) s += red[i2];
        int bidx = (blockIdx.z * TILES_Y + blockIdx.y) * TILES_X + blockIdx.x;
        g_part[bidx] = (double)s;
    }
}

__global__ void finalize_kernel(float* out, int n) {
    __shared__ double red[8];
    int tid = threadIdx.x;
    double s = 0.0;
    for (int i = tid; i < NBLOCKS; i += 256) s += g_part[i];
#pragma unroll
    for (int off = 16; off; off >>= 1)
        s += __shfl_xor_sync(0xffffffffu, s, off);
    if ((tid & 31) == 0) red[tid >> 5] = s;
    __syncthreads();
    if (tid == 0) {
        double t = 0.0;
#pragma unroll
        for (int i = 0; i < 8; ++i) t += red[i];
        float v = (float)(1.0 - t / TOTAL_OUT);
        for (int i = 0; i < n; ++i) out[i] = v;
    }
}

extern "C" void kernel_launch(void* const* d_in, const int* in_sizes, int n_in,
                              void* d_out, int out_size) {
    const float* pred   = (const float*)d_in[0];
    const float* target = (const float*)d_in[1];

    constexpr size_t SMEM = (size_t)(2 * IN_TY * SX_STRIDE + 5 * IN_TY * TX) * sizeof(float);
    cudaFuncSetAttribute(ssim_kernel, cudaFuncAttributeMaxDynamicSharedMemorySize, (int)SMEM);

    dim3 grid(TILES_X, TILES_Y, NCH);
    ssim_kernel<<<grid, 256, SMEM>>>(pred, target);
    finalize_kernel<<<1, 256>>>((float*)d_out, out_size);
}

// round 6
// speedup vs baseline: 1.4242x; 1.2662x over previous
#include <cuda_runtime.h>
#include <math.h>

// Problem geometry
#define H_IN   384
#define W_IN   512
#define H_OUT  374   // 384 - 10
#define W_OUT  502   // 512 - 10
#define NCH    48    // 16 * 3
#define TOTAL_OUT 9011904.0  // 48 * 374 * 502

// Tiling
#define TX 64        // output cols per tile
#define TY 48        // output rows per tile
#define IN_TX 74     // TX + 10
#define IN_TY 58     // TY + 10
#define SX_STRIDE 76 // padded row stride for input tiles
#define TILES_X 8    // ceil(502/64)
#define TILES_Y 8    // ceil(374/48)
#define ROWS_PER_THREAD 12   // TY / 4 strips

// Gaussian weights (win=11, sigma=1.5) as literals -> imm-form FFMA (rt_SMSP=1).
#define GW0 0.00102838f
#define GW1 0.00759874f
#define GW2 0.03600077f
#define GW3 0.10936073f
#define GW4 0.21300553f
#define GW5 0.26601171f

__device__ double g_sum = 0.0;

__global__ __launch_bounds__(256, 2)
void ssim_kernel(const float* __restrict__ X, const float* __restrict__ Y, int zbase) {
    constexpr float W[11] = {GW0, GW1, GW2, GW3, GW4, GW5, GW4, GW3, GW2, GW1, GW0};

    extern __shared__ float smem[];
    float* sX = smem;                          // 58*76
    float* sY = sX + IN_TY * SX_STRIDE;        // 58*76
    float* hB = sY + IN_TY * SX_STRIDE;        // 5 arrays of 58*64

    const int tid = threadIdx.x;
    const int tx0 = blockIdx.x * TX;
    const int ty0 = blockIdx.y * TY;
    const size_t chOff = (size_t)(zbase + blockIdx.z) * (H_IN * W_IN);
    const float* Xc = X + chOff;
    const float* Yc = Y + chOff;

    // ---- load input halo tiles as float2 (74 = 37 pairs; gc even so a pair
    // never straddles the W=512 edge). OOB -> zero (feeds only masked outputs).
    for (int i = tid; i < IN_TY * 37; i += 256) {
        int r = i / 37;
        int c2 = i - r * 37;
        int gr = ty0 + r;
        int gc = tx0 + 2 * c2;
        float2 xv = make_float2(0.f, 0.f);
        float2 yv = make_float2(0.f, 0.f);
        if (gr < H_IN && gc < W_IN) {
            xv = reinterpret_cast<const float2*>(Xc + gr * W_IN + gc)[0];
            yv = reinterpret_cast<const float2*>(Yc + gr * W_IN + gc)[0];
        }
        reinterpret_cast<float2*>(sX + r * SX_STRIDE + 2 * c2)[0] = xv;
        reinterpret_cast<float2*>(sY + r * SX_STRIDE + 2 * c2)[0] = yv;
    }
    __syncthreads();

    // ---- horizontal blur: 58 rows x 16 groups of 4 cols; imm-form FFMA taps
    for (int i = tid; i < IN_TY * 16; i += 256) {
        int r = i >> 4;
        int c0 = (i & 15) * 4;
        const float* rx = sX + r * SX_STRIDE + c0;
        const float* ry = sY + r * SX_STRIDE + c0;
        float vx[16], vy[16];
#pragma unroll
        for (int q = 0; q < 4; ++q) {
            float4 a = reinterpret_cast<const float4*>(rx)[q];
            float4 b = reinterpret_cast<const float4*>(ry)[q];
            vx[4*q+0] = a.x; vx[4*q+1] = a.y; vx[4*q+2] = a.z; vx[4*q+3] = a.w;
            vy[4*q+0] = b.x; vy[4*q+1] = b.y; vy[4*q+2] = b.z; vy[4*q+3] = b.w;
        }
        float pxx[14], pyy[14], pxy[14];
#pragma unroll
        for (int j = 0; j < 14; ++j) {
            pxx[j] = vx[j] * vx[j];
            pyy[j] = vy[j] * vy[j];
            pxy[j] = vx[j] * vy[j];
        }
        float m1[4] = {0,0,0,0}, m2[4] = {0,0,0,0};
        float xx[4] = {0,0,0,0}, yy[4] = {0,0,0,0}, xy[4] = {0,0,0,0};
#pragma unroll
        for (int k = 0; k < 11; ++k) {
#pragma unroll
            for (int o = 0; o < 4; ++o) {
                m1[o] = fmaf(W[k], vx[k + o],  m1[o]);
                m2[o] = fmaf(W[k], vy[k + o],  m2[o]);
                xx[o] = fmaf(W[k], pxx[k + o], xx[o]);
                yy[o] = fmaf(W[k], pyy[k + o], yy[o]);
                xy[o] = fmaf(W[k], pxy[k + o], xy[o]);
            }
        }
        int base = r * TX + c0;
        reinterpret_cast<float4*>(hB + 0 * IN_TY * TX + base)[0] = make_float4(m1[0], m1[1], m1[2], m1[3]);
        reinterpret_cast<float4*>(hB + 1 * IN_TY * TX + base)[0] = make_float4(m2[0], m2[1], m2[2], m2[3]);
        reinterpret_cast<float4*>(hB + 2 * IN_TY * TX + base)[0] = make_float4(xx[0], xx[1], xx[2], xx[3]);
        reinterpret_cast<float4*>(hB + 3 * IN_TY * TX + base)[0] = make_float4(yy[0], yy[1], yy[2], yy[3]);
        reinterpret_cast<float4*>(hB + 4 * IN_TY * TX + base)[0] = make_float4(xy[0], xy[1], xy[2], xy[3]);
    }
    __syncthreads();

    // ---- vertical blur + ssim map: 4 strips of 12 output rows, 64 cols
    float local = 0.f;
    {
        int c  = tid & 63;
        int r0 = (tid >> 6) * ROWS_PER_THREAD;
        const float* h0 = hB + 0 * IN_TY * TX + c;
        const float* h1 = hB + 1 * IN_TY * TX + c;
        const float* h2 = hB + 2 * IN_TY * TX + c;
        const float* h3 = hB + 3 * IN_TY * TX + c;
        const float* h4 = hB + 4 * IN_TY * TX + c;

        float a0[ROWS_PER_THREAD], a1[ROWS_PER_THREAD], a2[ROWS_PER_THREAD],
              a3[ROWS_PER_THREAD], a4[ROWS_PER_THREAD];
#pragma unroll
        for (int o = 0; o < ROWS_PER_THREAD; ++o) { a0[o] = a1[o] = a2[o] = a3[o] = a4[o] = 0.f; }

#pragma unroll
        for (int k = 0; k < ROWS_PER_THREAD + 10; ++k) {   // 22 input rows
            int off = (r0 + k) * TX;
            float v0 = h0[off];
            float v1 = h1[off];
            float v2 = h2[off];
            float v3 = h3[off];
            float v4 = h4[off];
#pragma unroll
            for (int o = 0; o < ROWS_PER_THREAD; ++o) {
                int t = k - o;
                if (t >= 0 && t < 11) {
                    a0[o] = fmaf(W[t], v0, a0[o]);
                    a1[o] = fmaf(W[t], v1, a1[o]);
                    a2[o] = fmaf(W[t], v2, a2[o]);
                    a3[o] = fmaf(W[t], v3, a3[o]);
                    a4[o] = fmaf(W[t], v4, a4[o]);
                }
            }
        }

        int gc = tx0 + c;
        const float C1 = 1e-4f, C2 = 9e-4f;
#pragma unroll
        for (int o = 0; o < ROWS_PER_THREAD; ++o) {
            int gr = ty0 + r0 + o;
            if (gr < H_OUT && gc < W_OUT) {
                float mu1 = a0[o], mu2 = a1[o];
                float mu1s = mu1 * mu1;
                float mu2s = mu2 * mu2;
                float m12  = mu1 * mu2;
                float s1  = a2[o] - mu1s;
                float s2  = a3[o] - mu2s;
                float s12 = a4[o] - m12;
                float num = (2.f * m12 + C1) * (2.f * s12 + C2);
                float den = (mu1s + mu2s + C1) * (s1 + s2 + C2);
                local += __fdividef(num, den);
            }
        }
    }

    // ---- block reduction + one double atomic per CTA
#pragma unroll
    for (int off = 16; off; off >>= 1)
        local += __shfl_xor_sync(0xffffffffu, local, off);

    __shared__ float red[8];
    int lane = tid & 31, wid = tid >> 5;
    if (lane == 0) red[wid] = local;
    __syncthreads();
    if (tid == 0) {
        float s = 0.f;
#pragma unroll
        for (int i2 = 0; i2 < 8; ++i2) s += red[i2];
        atomicAdd(&g_sum, (double)s);
    }
}

__global__ void finalize_kernel(float* out, int n) {
    if (threadIdx.x == 0) {
        double t = g_sum;
        float v = (float)(1.0 - t / TOTAL_OUT);
        for (int i = 0; i < n; ++i) out[i] = v;
        g_sum = 0.0;   // reset for next replay (deterministic across graph replays)
    }
}

extern "C" void kernel_launch(void* const* d_in, const int* in_sizes, int n_in,
                              void* d_out, int out_size) {
    const float* pred   = (const float*)d_in[0];
    const float* target = (const float*)d_in[1];

    constexpr size_t SMEM = (size_t)(2 * IN_TY * SX_STRIDE + 5 * IN_TY * TX) * sizeof(float);
    cudaFuncSetAttribute(ssim_kernel, cudaFuncAttributeMaxDynamicSharedMemorySize, (int)SMEM);

    // Two z-halves: 3-launch pattern puts the hot kernel at position 0 mod 3
    // so ncu (-s 5 -c 1) captures it instead of the epilogue.
    dim3 grid(TILES_X, TILES_Y, NCH / 2);
    ssim_kernel<<<grid, 256, SMEM>>>(pred, target, 0);
    ssim_kernel<<<grid, 256, SMEM>>>(pred, target, NCH / 2);
    finalize_kernel<<<1, 32>>>((float*)d_out, out_size);
}

// round 7
// speedup vs baseline: 2.0811x; 1.4612x over previous
#include <cuda_runtime.h>
#include <math.h>

// Problem geometry
#define H_IN   384
#define W_IN   512
#define H_OUT  374   // 384 - 10
#define W_OUT  502   // 512 - 10
#define NCH    48    // 16 * 3
#define TOTAL_OUT 9011904.0  // 48 * 374 * 502

// Tiling
#define TX 64        // output cols per tile
#define TY 48        // output rows per tile
#define IN_TY 58     // TY + 10
#define TILES_X 8    // ceil(502/64)
#define TILES_Y 8    // ceil(374/48)
#define ROWS_PER_THREAD 12   // TY / 4 strips

// Gaussian weights (win=11, sigma=1.5) as literals -> imm-form FFMA (rt_SMSP=1).
#define GW0 0.00102838f
#define GW1 0.00759874f
#define GW2 0.03600077f
#define GW3 0.10936073f
#define GW4 0.21300553f
#define GW5 0.26601171f

__device__ double g_sum = 0.0;

__global__ __launch_bounds__(256, 3)
void ssim_kernel(const float* __restrict__ X, const float* __restrict__ Y, int zbase) {
    constexpr float W[11] = {GW0, GW1, GW2, GW3, GW4, GW5, GW4, GW3, GW2, GW1, GW0};

    // smem: only the 5 h-blurred fields (58 x 64 each) = 74240 B -> 3 CTAs/SM
    extern __shared__ float hB[];

    const int tid = threadIdx.x;
    const int tx0 = blockIdx.x * TX;
    const int ty0 = blockIdx.y * TY;
    const size_t chOff = (size_t)(zbase + blockIdx.z) * (H_IN * W_IN);
    const float* Xc = X + chOff;
    const float* Yc = Y + chOff;

    // ---- horizontal blur straight from gmem (L1/L2-resident working set):
    // 58 rows x 16 groups of 4 output cols. Window = 14 elems = 4 float4s.
    // Masked OOB -> 0 (feeds only masked outputs). All taps imm-form FFMA.
    for (int i = tid; i < IN_TY * 16; i += 256) {
        int r = i >> 4;
        int c0 = (i & 15) * 4;
        int gr = ty0 + r;
        bool rok = (gr < H_IN);
        const float* rx = Xc + gr * W_IN + tx0 + c0;
        const float* ry = Yc + gr * W_IN + tx0 + c0;

        float vx[16], vy[16];
#pragma unroll
        for (int q = 0; q < 4; ++q) {
            int gc = tx0 + c0 + 4 * q;           // multiple of 4, never straddles 512
            float4 a = make_float4(0.f, 0.f, 0.f, 0.f);
            float4 b = make_float4(0.f, 0.f, 0.f, 0.f);
            if (rok && gc < W_IN) {
                a = reinterpret_cast<const float4*>(rx)[q];
                b = reinterpret_cast<const float4*>(ry)[q];
            }
            vx[4*q+0] = a.x; vx[4*q+1] = a.y; vx[4*q+2] = a.z; vx[4*q+3] = a.w;
            vy[4*q+0] = b.x; vy[4*q+1] = b.y; vy[4*q+2] = b.z; vy[4*q+3] = b.w;
        }
        float pxx[14], pyy[14], pxy[14];
#pragma unroll
        for (int j = 0; j < 14; ++j) {
            pxx[j] = vx[j] * vx[j];
            pyy[j] = vy[j] * vy[j];
            pxy[j] = vx[j] * vy[j];
        }
        float m1[4] = {0,0,0,0}, m2[4] = {0,0,0,0};
        float xx[4] = {0,0,0,0}, yy[4] = {0,0,0,0}, xy[4] = {0,0,0,0};
#pragma unroll
        for (int k = 0; k < 11; ++k) {
#pragma unroll
            for (int o = 0; o < 4; ++o) {
                m1[o] = fmaf(W[k], vx[k + o],  m1[o]);
                m2[o] = fmaf(W[k], vy[k + o],  m2[o]);
                xx[o] = fmaf(W[k], pxx[k + o], xx[o]);
                yy[o] = fmaf(W[k], pyy[k + o], yy[o]);
                xy[o] = fmaf(W[k], pxy[k + o], xy[o]);
            }
        }
        int base = r * TX + c0;
        reinterpret_cast<float4*>(hB + 0 * IN_TY * TX + base)[0] = make_float4(m1[0], m1[1], m1[2], m1[3]);
        reinterpret_cast<float4*>(hB + 1 * IN_TY * TX + base)[0] = make_float4(m2[0], m2[1], m2[2], m2[3]);
        reinterpret_cast<float4*>(hB + 2 * IN_TY * TX + base)[0] = make_float4(xx[0], xx[1], xx[2], xx[3]);
        reinterpret_cast<float4*>(hB + 3 * IN_TY * TX + base)[0] = make_float4(yy[0], yy[1], yy[2], yy[3]);
        reinterpret_cast<float4*>(hB + 4 * IN_TY * TX + base)[0] = make_float4(xy[0], xy[1], xy[2], xy[3]);
    }
    __syncthreads();

    // ---- vertical blur + ssim map: 4 strips of 12 output rows, 64 cols
    float local = 0.f;
    {
        int c  = tid & 63;
        int r0 = (tid >> 6) * ROWS_PER_THREAD;
        const float* h0 = hB + 0 * IN_TY * TX + c;
        const float* h1 = hB + 1 * IN_TY * TX + c;
        const float* h2 = hB + 2 * IN_TY * TX + c;
        const float* h3 = hB + 3 * IN_TY * TX + c;
        const float* h4 = hB + 4 * IN_TY * TX + c;

        float a0[ROWS_PER_THREAD], a1[ROWS_PER_THREAD], a2[ROWS_PER_THREAD],
              a3[ROWS_PER_THREAD], a4[ROWS_PER_THREAD];
#pragma unroll
        for (int o = 0; o < ROWS_PER_THREAD; ++o) { a0[o] = a1[o] = a2[o] = a3[o] = a4[o] = 0.f; }

#pragma unroll
        for (int k = 0; k < ROWS_PER_THREAD + 10; ++k) {   // 22 input rows
            int off = (r0 + k) * TX;
            float v0 = h0[off];
            float v1 = h1[off];
            float v2 = h2[off];
            float v3 = h3[off];
            float v4 = h4[off];
#pragma unroll
            for (int o = 0; o < ROWS_PER_THREAD; ++o) {
                int t = k - o;
                if (t >= 0 && t < 11) {
                    a0[o] = fmaf(W[t], v0, a0[o]);
                    a1[o] = fmaf(W[t], v1, a1[o]);
                    a2[o] = fmaf(W[t], v2, a2[o]);
                    a3[o] = fmaf(W[t], v3, a3[o]);
                    a4[o] = fmaf(W[t], v4, a4[o]);
                }
            }
        }

        int gc = tx0 + c;
        const float C1 = 1e-4f, C2 = 9e-4f;
#pragma unroll
        for (int o = 0; o < ROWS_PER_THREAD; ++o) {
            int gr = ty0 + r0 + o;
            if (gr < H_OUT && gc < W_OUT) {
                float mu1 = a0[o], mu2 = a1[o];
                float mu1s = mu1 * mu1;
                float mu2s = mu2 * mu2;
                float m12  = mu1 * mu2;
                float s1  = a2[o] - mu1s;
                float s2  = a3[o] - mu2s;
                float s12 = a4[o] - m12;
                float num = (2.f * m12 + C1) * (2.f * s12 + C2);
                float den = (mu1s + mu2s + C1) * (s1 + s2 + C2);
                local += __fdividef(num, den);
            }
        }
    }

    // ---- block reduction + one double atomic per CTA
#pragma unroll
    for (int off = 16; off; off >>= 1)
        local += __shfl_xor_sync(0xffffffffu, local, off);

    __shared__ float red[8];
    int lane = tid & 31, wid = tid >> 5;
    if (lane == 0) red[wid] = local;
    __syncthreads();
    if (tid == 0) {
        float s = 0.f;
#pragma unroll
        for (int i2 = 0; i2 < 8; ++i2) s += red[i2];
        atomicAdd(&g_sum, (double)s);
    }
}

__global__ void finalize_kernel(float* out, int n) {
    if (threadIdx.x == 0) {
        double t = g_sum;
        float v = (float)(1.0 - t / TOTAL_OUT);
        for (int i = 0; i < n; ++i) out[i] = v;
        g_sum = 0.0;   // reset for next replay (deterministic across graph replays)
    }
}

extern "C" void kernel_launch(void* const* d_in, const int* in_sizes, int n_in,
                              void* d_out, int out_size) {
    const float* pred   = (const float*)d_in[0];
    const float* target = (const float*)d_in[1];

    constexpr size_t SMEM = (size_t)(5 * IN_TY * TX) * sizeof(float);   // 74240 B
    cudaFuncSetAttribute(ssim_kernel, cudaFuncAttributeMaxDynamicSharedMemorySize, (int)SMEM);

    // Two z-halves: keeps the hot kernel at sample position 0 mod 3 for ncu.
    dim3 grid(TILES_X, TILES_Y, NCH / 2);
    ssim_kernel<<<grid, 256, SMEM>>>(pred, target, 0);
    ssim_kernel<<<grid, 256, SMEM>>>(pred, target, NCH / 2);
    finalize_kernel<<<1, 32>>>((float*)d_out, out_size);
}